// round 13
// baseline (speedup 1.0000x reference)
#include <cuda_runtime.h>
#include <math.h>

#define NN 20000
#define ED 160000
#define MAXE 160000
#define G 444
#define T 256
#define GT (G * T)
#define MW 625   /* bitmask words for NN bits */
#define SMALL_L 16

/* ------------------------------ scratch ------------------------------ */
__device__ int g_bar_cnt = 0;
__device__ int g_bar_gen = 0;

__device__ int g_cnt[NN], g_fill1[NN], g_fill2[NN], g_fill3[NN], g_fill4[NN];
__device__ int g_offA[NN], g_offB[NN];
__device__ int g_bucket[ED];
__device__ int g_csrc[MAXE], g_cdst[MAXE];
__device__ int g_ndeg[NN], g_incoff[NN];
__device__ int g_inc[2 * MAXE];
__device__ int g_inco[2 * MAXE];
__device__ float g_incd[2 * MAXE];
__device__ float g_dinv[MAXE];
__device__ float g_xW[NN * 64];
__device__ float g_aggN[NN * 64];
__device__ float g_hE[MAXE * 64];          /* conv1-z cache */
__device__ double g_p1[G * 64], g_p2[G * 64];
__device__ float g_mu[64], g_istd[64];
__device__ float g_h2[MAXE], g_agg2[NN], g_score[MAXE];
__device__ unsigned g_keyv[MAXE];
__device__ int g_hist2[65536];
__device__ unsigned long long g_packed[NN];
__device__ int g_bcnt[G], g_boff[G];
__device__ int g_n2c[NN], g_flag[NN], g_rankv[NN], g_uniq[NN], g_ni[NN];
__device__ int g_pcnt[NN], g_poff[NN], g_pnode[NN];
__device__ int g_ecnt[NN], g_eoffA[NN], g_ucnt[NN], g_eoffB[NN];
__device__ int g_E, g_M, g_P, g_krem;
__device__ unsigned g_prefix;

/* ------------------------------ grid barrier ------------------------------ */
__device__ __forceinline__ void gsync() {
    __syncthreads();
    if (threadIdx.x == 0) {
        int gen = *(volatile int*)&g_bar_gen;
        __threadfence();
        if (atomicAdd(&g_bar_cnt, 1) == G - 1) {
            g_bar_cnt = 0;
            __threadfence();
            *(volatile int*)&g_bar_gen = gen + 1;
        } else {
            while (*(volatile int*)&g_bar_gen == gen) __nanosleep(64);
        }
    }
    __syncthreads();
}

/* ---------------- block exclusive scan over T threads (shuffle) ---------------- */
__device__ __forceinline__ int bscan_excl(int v, int* sh, int* total) {
    int t = threadIdx.x, lane = t & 31, w = t >> 5;
    int x = v;
    #pragma unroll
    for (int o = 1; o < 32; o <<= 1) { int y = __shfl_up_sync(0xffffffffu, x, o); if (lane >= o) x += y; }
    if (lane == 31) sh[w] = x;
    __syncthreads();
    if (w == 0) {
        int s = (lane < 8) ? sh[lane] : 0;
        #pragma unroll
        for (int o = 1; o < 8; o <<= 1) { int y = __shfl_up_sync(0xffffffffu, s, o); if (lane >= o) s += y; }
        if (lane < 8) sh[lane] = s;
    }
    __syncthreads();
    *total = sh[7];
    int pre = (w == 0) ? 0 : sh[w - 1];
    return pre + x - v;
}

/* ---------------- block-0 exclusive scan over array ---------------- */
__device__ void scan_b0(const int* in, int* out, int n, int code, char* SMEM) {
    if (blockIdx.x != 0) return;
    int* sh = (int*)SMEM;
    int t = threadIdx.x;
    int per = (n + T - 1) / T;
    int lo = t * per; if (lo > n) lo = n;
    int hi = lo + per; if (hi > n) hi = n;
    int s = 0;
    for (int i = lo; i < hi; i++) s += __ldcg(in + i);
    int total;
    int excl = bscan_excl(s, sh, &total);
    if (t == 0) {
        if (code == 1) g_E = total;
        else if (code == 2) g_M = total;
        else if (code == 3) g_P = total;
    }
    int acc = excl;
    for (int i = lo; i < hi; i++) { int v = __ldcg(in + i); out[i] = acc; acc += v; }
}

/* ---------------- 16-bit radix pick (block 0) ---------------- */
__device__ void pick16_b0(int hi, char* SMEM) {
    if (blockIdx.x != 0) return;
    int* seg  = (int*)SMEM;
    int* sbin = (int*)SMEM + 256;
    int* info = (int*)SMEM + 512;
    int t = threadIdx.x;
    int s = 0, base = t * 256;
    for (int i = 0; i < 256; i++) s += __ldcg(&g_hist2[base + i]);
    seg[t] = s;
    __syncthreads();
    if (t == 0) {
        int krem = __ldcg(&g_krem);
        int cum = 0, sid = 0;
        for (int sg = 255; sg >= 0; sg--) { int h = seg[sg]; if (cum + h >= krem) { sid = sg; break; } cum += h; }
        info[0] = sid; info[1] = cum;
    }
    __syncthreads();
    int sid = info[0];
    sbin[t] = __ldcg(&g_hist2[sid * 256 + t]);
    __syncthreads();
    if (t == 0) {
        int krem = __ldcg(&g_krem);
        int cum = info[1], chosen = sid * 256;
        for (int bn = 255; bn >= 0; bn--) { int h = sbin[bn]; if (cum + h >= krem) { chosen = sid * 256 + bn; break; } cum += h; }
        g_prefix = __ldcg(&g_prefix) | ((unsigned)chosen << (hi ? 16 : 0));
        g_krem = krem - cum;
    }
    __syncthreads();
    if (hi) for (int i = t; i < 65536; i += T) g_hist2[i] = 0;
}

/* ------------------------------ megakernel ------------------------------ */
extern "C" __global__ void __launch_bounds__(T, 3)
mega(const float* __restrict__ x, const float* __restrict__ W1, const float* __restrict__ b1,
     const float* __restrict__ gamma1, const float* __restrict__ beta1,
     const float* __restrict__ W2, const float* __restrict__ b2,
     const int* __restrict__ ei, const int* __restrict__ batch,
     float* __restrict__ out) {
    __shared__ __align__(16) char SMEM[40960];
    const int t = threadIdx.x;
    const int b = blockIdx.x;
    const int gtid = b * T + t;

    /* ---- ph0: init ---- */
    for (int i = gtid; i < NN; i += GT) {
        g_cnt[i] = 0; g_fill1[i] = 0; g_fill2[i] = 0; g_fill3[i] = 0; g_fill4[i] = 0;
        g_ndeg[i] = 0; g_ecnt[i] = 0; g_pcnt[i] = 0; g_flag[i] = 0; g_ucnt[i] = 0;
        g_packed[i] = ~0ull;
    }
    for (int i = gtid; i < 65536; i += GT) g_hist2[i] = 0;
    gsync();

    /* ---- ph1: histogram of raw undirected edges by src ---- */
    for (int i = gtid; i < ED; i += GT) {
        int s = ei[i], d = ei[ED + i];
        if (s < d) atomicAdd(&g_cnt[s], 1);
    }
    gsync();

    /* ---- ph2: scan cnt -> offA ---- */
    scan_b0(g_cnt, g_offA, NN, 0, SMEM);
    gsync();

    /* ---- ph3: scatter to buckets ---- */
    for (int i = gtid; i < ED; i += GT) {
        int s = ei[i], d = ei[ED + i];
        if (s < d) {
            int pos = g_offA[s] + atomicAdd(&g_fill1[s], 1);
            g_bucket[pos] = d;
        }
    }
    gsync();

    /* ---- ph4: per-node sort + dedup (registerized) ---- */
    for (int u = gtid; u < NN; u += GT) {
        int o = g_offA[u], L = g_cnt[u], m = 0;
        if (L <= 24) {
            int buf[24];
            for (int i = 0; i < L; i++) buf[i] = g_bucket[o + i];
            for (int i = 1; i < L; i++) {
                int key = buf[i]; int j = i - 1;
                while (j >= 0 && buf[j] > key) { buf[j + 1] = buf[j]; j--; }
                buf[j + 1] = key;
            }
            int last = -1;
            for (int i = 0; i < L; i++) {
                int v = buf[i];
                if (v != last) { g_bucket[o + m++] = v; last = v; }
            }
        } else {
            for (int i = 1; i < L; i++) {
                int key = g_bucket[o + i]; int j = i - 1;
                while (j >= 0 && g_bucket[o + j] > key) { g_bucket[o + j + 1] = g_bucket[o + j]; j--; }
                g_bucket[o + j + 1] = key;
            }
            for (int i = 0; i < L; i++) {
                int v = g_bucket[o + i];
                if (m == 0 || v != g_bucket[o + m - 1]) g_bucket[o + m++] = v;
            }
        }
        g_cnt[u] = m;
    }
    gsync();

    /* ---- ph5: scan deduped counts -> offB, total E ---- */
    scan_b0(g_cnt, g_offB, NN, 1, SMEM);
    gsync();

    /* ---- ph6: compact clean edge list + node degrees ---- */
    for (int u = gtid; u < NN; u += GT) {
        int L = g_cnt[u], ob = g_offB[u], oa = g_offA[u];
        for (int j = 0; j < L; j++) {
            int d = g_bucket[oa + j];
            g_csrc[ob + j] = u; g_cdst[ob + j] = d;
            atomicAdd(&g_ndeg[d], 1);
        }
        if (L) atomicAdd(&g_ndeg[u], L);
    }
    gsync();

    /* ---- ph7: scan ndeg -> incoff ---- */
    scan_b0(g_ndeg, g_incoff, NN, 0, SMEM);
    gsync();

    /* ---- ph8: incidence scatter + dinv (split segments) ---- */
    {
        int E = g_E;
        for (int e = gtid; e < E; e += GT) {
            int u = g_csrc[e], v = g_cdst[e];
            int srcbase = g_incoff[u] + (g_ndeg[u] - g_cnt[u]);
            g_inc[srcbase + (e - g_offB[u])] = e;                 /* no atomic */
            int p2 = g_incoff[v] + atomicAdd(&g_fill2[v], 1); g_inc[p2] = e;
            int deg = g_ndeg[u] + g_ndeg[v] - 1;
            if (deg < 1) deg = 1;
            g_dinv[e] = 1.0f / sqrtf((float)deg);
        }
    }
    gsync();

    /* ---- ph9: sort ONLY dst-segment + fill (other,dinv) slots + GEMM ---- */
    for (int u = gtid; u < NN; u += GT) {
        int o = g_incoff[u], L = g_ndeg[u];
        int dl = L - g_cnt[u];
        if (dl > 1) {
            if (dl <= 24) {
                int buf[24];
                for (int i = 0; i < dl; i++) buf[i] = g_inc[o + i];
                for (int i = 1; i < dl; i++) {
                    int key = buf[i]; int j = i - 1;
                    while (j >= 0 && buf[j] > key) { buf[j + 1] = buf[j]; j--; }
                    buf[j + 1] = key;
                }
                for (int i = 0; i < dl; i++) g_inc[o + i] = buf[i];
            } else {
                for (int i = 1; i < dl; i++) {
                    int key = g_inc[o + i]; int j = i - 1;
                    while (j >= 0 && g_inc[o + j] > key) { g_inc[o + j + 1] = g_inc[o + j]; j--; }
                    g_inc[o + j + 1] = key;
                }
            }
        }
        for (int j = 0; j < L; j++) {
            int e = g_inc[o + j];
            g_inco[o + j] = g_csrc[e] + g_cdst[e] - u;
            g_incd[o + j] = g_dinv[e];
        }
    }
    {
        float* sW = (float*)SMEM;
        float* sx = (float*)(SMEM + 32768);
        __syncthreads();
        for (int i = t; i < 128 * 64; i += T) sW[i] = W1[i];
        __syncthreads();
        int c = t & 63, q = t >> 6;
        int rb = q * 4;
        for (int grp = b; grp < NN / 16; grp += G) {
            int r0 = grp * 16;
            float4* sx4 = (float4*)sx;
            const float4* x4 = (const float4*)(x + (long)r0 * 128);
            for (int i = t; i < 512; i += T) sx4[i] = x4[i];
            __syncthreads();
            float a0 = 0.f, a1 = 0.f, a2 = 0.f, a3 = 0.f;
            #pragma unroll 4
            for (int k2 = 0; k2 < 128; k2++) {
                float w = sW[k2 * 64 + c];
                a0 += sx[(rb + 0) * 128 + k2] * w;
                a1 += sx[(rb + 1) * 128 + k2] * w;
                a2 += sx[(rb + 2) * 128 + k2] * w;
                a3 += sx[(rb + 3) * 128 + k2] * w;
            }
            g_xW[(r0 + rb + 0) * 64 + c] = a0;
            g_xW[(r0 + rb + 1) * 64 + c] = a1;
            g_xW[(r0 + rb + 2) * 64 + c] = a2;
            g_xW[(r0 + rb + 3) * 64 + c] = a3;
            __syncthreads();
        }
    }
    gsync();

    /* ---- ph11: aggN, float4 channels ---- */
    {
        const float4* xW4 = (const float4*)g_xW;
        float4* aN4 = (float4*)g_aggN;
        for (int idx = gtid; idx < NN * 16; idx += GT) {
            int n = idx >> 4, cg = idx & 15;
            int o = g_incoff[n], L = g_ndeg[n];
            float4 xn = xW4[n * 16 + cg];
            float4 s = make_float4(0.f, 0.f, 0.f, 0.f);
            for (int j = 0; j < L; j++) {
                int other = g_inco[o + j];
                float di = g_incd[o + j];
                float4 xo = xW4[other * 16 + cg];
                s.x += di * (0.5f * (xn.x + xo.x));
                s.y += di * (0.5f * (xn.y + xo.y));
                s.z += di * (0.5f * (xn.z + xo.z));
                s.w += di * (0.5f * (xn.w + xo.w));
            }
            aN4[idx] = s;
        }
    }
    gsync();

    /* ---- ph12a: per-edge conv1-z compute -> z-cache (no stats) ---- */
    {
        int E = g_E;
        const float4* xW4 = (const float4*)g_xW;
        const float4* aN4 = (const float4*)g_aggN;
        float4* hE4 = (float4*)g_hE;
        float4* sb1 = (float4*)SMEM;
        if (t < 16) sb1[t] = ((const float4*)b1)[t];
        __syncthreads();
        for (int e = gtid; e < E; e += GT) {
            int u = g_csrc[e], v = g_cdst[e];
            float di = g_dinv[e];
            #pragma unroll
            for (int cg = 0; cg < 16; cg++) {
                float4 xu = xW4[u * 16 + cg], xv = xW4[v * 16 + cg];
                float4 au = aN4[u * 16 + cg], av = aN4[v * 16 + cg];
                float4 bb = sb1[cg];
                float4 z;
                { float h = 0.5f * (xu.x + xv.x); z.x = di * (au.x + av.x) - di * di * h + bb.x; }
                { float h = 0.5f * (xu.y + xv.y); z.y = di * (au.y + av.y) - di * di * h + bb.y; }
                { float h = 0.5f * (xu.z + xv.z); z.z = di * (au.z + av.z) - di * di * h + bb.z; }
                { float h = 0.5f * (xu.w + xv.w); z.w = di * (au.w + av.w) - di * di * h + bb.w; }
                hE4[e * 16 + cg] = z;
            }
        }
    }
    gsync();

    /* ---- ph12b: per-CHANNEL BN stats from z-cache (c = idx&63 fixed/thread,
       identical ordering to the last passing kernel) ---- */
    {
        int E = g_E;
        double s = 0.0, s2 = 0.0;
        for (int idx = gtid; idx < E * 64; idx += GT) {
            double zd = (double)__ldcg(&g_hE[idx]);
            s += zd; s2 += zd * zd;
        }
        double* sA = (double*)SMEM;
        double* sB = (double*)(SMEM + 2048);
        sA[t] = s; sB[t] = s2;
        __syncthreads();
        if (t < 64) {
            g_p1[b * 64 + t] = sA[t] + sA[t + 64] + sA[t + 128] + sA[t + 192];
            g_p2[b * 64 + t] = sB[t] + sB[t + 64] + sB[t + 128] + sB[t + 192];
        }
    }
    gsync();

    /* ---- ph13: BN finalize (per channel) + top-k init ---- */
    if (b == 0 && t < 64) {
        double s = 0.0, s2 = 0.0;
        for (int bb = 0; bb < G; bb++) { s += g_p1[bb * 64 + t]; s2 += g_p2[bb * 64 + t]; }
        double Ed = (double)g_E;
        double mu = s / Ed;
        double var = s2 / Ed - mu * mu;
        g_mu[t] = (float)mu;
        g_istd[t] = (float)(1.0 / sqrt(var + 1e-5));
        if (t == 0) {
            int E = g_E;
            int k = E / 2;
            if (k > NN / 2) k = NN / 2;
            if (k < 1) k = 1;
            g_krem = k; g_prefix = 0u;
        }
    }
    gsync();

    /* ---- ph14: per-edge BN+ReLU+dot from z-cache (exact old reduction tree) ---- */
    {
        int E = g_E;
        float* sga = (float*)SMEM;
        float* sbe = sga + 64;
        float* sw2 = sbe + 64;
        float* smu = sw2 + 64;
        float* sis = smu + 64;
        if (t < 64) { sga[t] = gamma1[t]; sbe[t] = beta1[t]; sw2[t] = W2[t]; smu[t] = g_mu[t]; sis[t] = g_istd[t]; }
        __syncthreads();
        const float4* hE4 = (const float4*)g_hE;
        for (int e = gtid; e < E; e += GT) {
            float p[32];
            #pragma unroll
            for (int cg = 0; cg < 8; cg++) {
                float4 za = hE4[e * 16 + cg];
                float4 zb = hE4[e * 16 + 8 + cg];
                int c0 = 4 * cg;
                {
                    float a0 = fmaxf(sga[c0] * (za.x - smu[c0]) * sis[c0] + sbe[c0], 0.f);
                    float a1 = fmaxf(sga[c0 + 32] * (zb.x - smu[c0 + 32]) * sis[c0 + 32] + sbe[c0 + 32], 0.f);
                    p[c0] = a0 * sw2[c0] + a1 * sw2[c0 + 32];
                }
                {
                    float a0 = fmaxf(sga[c0 + 1] * (za.y - smu[c0 + 1]) * sis[c0 + 1] + sbe[c0 + 1], 0.f);
                    float a1 = fmaxf(sga[c0 + 33] * (zb.y - smu[c0 + 33]) * sis[c0 + 33] + sbe[c0 + 33], 0.f);
                    p[c0 + 1] = a0 * sw2[c0 + 1] + a1 * sw2[c0 + 33];
                }
                {
                    float a0 = fmaxf(sga[c0 + 2] * (za.z - smu[c0 + 2]) * sis[c0 + 2] + sbe[c0 + 2], 0.f);
                    float a1 = fmaxf(sga[c0 + 34] * (zb.z - smu[c0 + 34]) * sis[c0 + 34] + sbe[c0 + 34], 0.f);
                    p[c0 + 2] = a0 * sw2[c0 + 2] + a1 * sw2[c0 + 34];
                }
                {
                    float a0 = fmaxf(sga[c0 + 3] * (za.w - smu[c0 + 3]) * sis[c0 + 3] + sbe[c0 + 3], 0.f);
                    float a1 = fmaxf(sga[c0 + 35] * (zb.w - smu[c0 + 35]) * sis[c0 + 35] + sbe[c0 + 35], 0.f);
                    p[c0 + 3] = a0 * sw2[c0 + 3] + a1 * sw2[c0 + 35];
                }
            }
            #pragma unroll
            for (int l = 0; l < 16; l++) p[l] += p[l + 16];
            #pragma unroll
            for (int l = 0; l < 8; l++) p[l] += p[l + 8];
            #pragma unroll
            for (int l = 0; l < 4; l++) p[l] += p[l + 4];
            p[0] += p[2]; p[1] += p[3];
            g_h2[e] = p[0] + p[1];
        }
    }
    gsync();

    /* ---- ph15: agg2 per node ---- */
    for (int n = gtid; n < NN; n += GT) {
        int o = g_incoff[n], L = g_ndeg[n];
        float s = 0.f;
        for (int j = 0; j < L; j++) { int e = g_inc[o + j]; s += g_incd[o + j] * g_h2[e]; }
        g_agg2[n] = s;
    }
    gsync();

    /* ---- ph16: scores + 16-bit radix hist (hi) ---- */
    {
        int E = g_E;
        float bias2 = b2[0];
        for (int e = gtid; e < E; e += GT) {
            float di = g_dinv[e];
            float z = di * (g_agg2[g_csrc[e]] + g_agg2[g_cdst[e]]) - di * di * g_h2[e] + bias2;
            float s = 1.0f / (1.0f + expf(-z));
            g_score[e] = s;
            unsigned kk = __float_as_uint(s);
            g_keyv[e] = kk;
            atomicAdd(&g_hist2[kk >> 16], 1);
        }
    }
    gsync();

    /* ---- ph17: pick hi 16 bits ---- */
    pick16_b0(1, SMEM);
    gsync();

    /* ---- ph18: hist low 16 bits for matching hi prefix ---- */
    {
        int E = g_E;
        unsigned hiP = __ldcg(&g_prefix) >> 16;
        for (int e = gtid; e < E; e += GT) {
            unsigned kk = g_keyv[e];
            if ((kk >> 16) == hiP) atomicAdd(&g_hist2[kk & 0xFFFFu], 1);
        }
    }
    gsync();

    /* ---- ph19: pick low 16 bits ---- */
    pick16_b0(0, SMEM);
    gsync();

    /* ---- ph24: strictly-greater -> atomicMin cluster; count eq per block ---- */
    {
        int E = g_E;
        unsigned Tp = __ldcg(&g_prefix);
        int cb = (E + G - 1) / G;
        int lo = b * cb, hi = lo + cb; if (hi > E) hi = E;
        int cnt = 0;
        for (int base = lo; base < hi; base += T) {
            int i = base + t;
            if (i < hi) {
                unsigned kk = g_keyv[i];
                if (kk > Tp) {
                    unsigned long long pk = (((unsigned long long)kk) << 32) | (unsigned)(0xFFFFFFFFu - (unsigned)i);
                    atomicMin(&g_packed[g_cdst[i]], pk);
                }
                if (kk == Tp) cnt++;
            }
        }
        int* sh = (int*)SMEM;
        int total;
        bscan_excl(cnt, sh, &total);
        if (t == 0) g_bcnt[b] = total;
    }
    gsync();

    /* ---- ph25: scan bcnt -> boff ---- */
    scan_b0(g_bcnt, g_boff, G, 0, SMEM);
    gsync();

    /* ---- ph26: eq keys, index-ordered rank < krem -> select ---- */
    {
        int E = g_E;
        unsigned Tp = __ldcg(&g_prefix);
        int krem = __ldcg(&g_krem);
        int cb = (E + G - 1) / G;
        int lo = b * cb, hi = lo + cb; if (hi > E) hi = E;
        int* ws = (int*)SMEM;
        int* scarry = (int*)SMEM + 16;
        if (t == 0) *scarry = 0;
        __syncthreads();
        int lane = t & 31, wid = t >> 5;
        for (int base = lo; base < hi; base += T) {
            int i = base + t;
            int eq = (i < hi && g_keyv[i] == Tp) ? 1 : 0;
            unsigned bal = __ballot_sync(0xffffffffu, eq);
            if (lane == 0) ws[wid] = __popc(bal);
            __syncthreads();
            int pre = 0;
            for (int k = 0; k < wid; k++) pre += ws[k];
            int lexcl = pre + __popc(bal & ((1u << lane) - 1u));
            if (eq) {
                int rank = g_boff[b] + *scarry + lexcl;
                if (rank < krem) {
                    unsigned long long pk = (((unsigned long long)Tp) << 32) | (unsigned)(0xFFFFFFFFu - (unsigned)i);
                    atomicMin(&g_packed[g_cdst[i]], pk);
                }
            }
            __syncthreads();
            if (t == 0) {
                int tot = 0;
                #pragma unroll
                for (int k = 0; k < 8; k++) tot += ws[k];
                *scarry += tot;
            }
            __syncthreads();
        }
    }
    gsync();

    /* ---- ph27: node -> cluster label ---- */
    for (int n = gtid; n < NN; n += GT) {
        unsigned long long pk = g_packed[n];
        int v;
        if (pk != ~0ull) {
            unsigned e = 0xFFFFFFFFu - (unsigned)(pk & 0xFFFFFFFFull);
            v = g_csrc[e];
        } else v = n;
        g_n2c[n] = v;
        g_flag[v] = 1;
    }
    gsync();

    /* ---- ph28: scan flag -> rankv, total M ---- */
    scan_b0(g_flag, g_rankv, NN, 2, SMEM);
    gsync();

    /* ---- ph29: maps + pool counts ---- */
    for (int n = gtid; n < NN; n += GT) {
        if (g_flag[n]) g_uniq[g_rankv[n]] = n;
        int m = g_rankv[g_n2c[n]];
        g_ni[n] = m;
        atomicAdd(&g_pcnt[m], 1);
    }
    gsync();

    /* ---- ph30: scan pcnt -> poff ---- */
    scan_b0(g_pcnt, g_poff, NN, 0, SMEM);
    gsync();

    /* ---- ph31: scatter members + pooled-edge histogram (merged) ---- */
    for (int n = gtid; n < NN; n += GT) {
        int m = g_ni[n];
        int pos = g_poff[m] + atomicAdd(&g_fill3[m], 1);
        g_pnode[pos] = n;
    }
    for (int i = gtid; i < ED; i += GT) {
        int ns = g_ni[ei[i]], nd = g_ni[ei[ED + i]];
        if (ns != nd) atomicAdd(&g_ecnt[ns], 1);
    }
    gsync();

    /* ---- ph32: scan ecnt -> eoffA (b0) + member-list sorts ---- */
    scan_b0(g_ecnt, g_eoffA, NN, 0, SMEM);
    {
        int M = g_M;
        for (int m = gtid; m < M; m += GT) {
            int o = g_poff[m], L = g_pcnt[m];
            if (L <= 16) {
                int buf[16];
                for (int i = 0; i < L; i++) buf[i] = g_pnode[o + i];
                for (int i = 1; i < L; i++) {
                    int key = buf[i]; int j = i - 1;
                    while (j >= 0 && buf[j] > key) { buf[j + 1] = buf[j]; j--; }
                    buf[j + 1] = key;
                }
                for (int i = 0; i < L; i++) g_pnode[o + i] = buf[i];
            } else {
                for (int i = 1; i < L; i++) {
                    int key = g_pnode[o + i]; int j = i - 1;
                    while (j >= 0 && g_pnode[o + j] > key) { g_pnode[o + j + 1] = g_pnode[o + j]; j--; }
                    g_pnode[o + j + 1] = key;
                }
            }
        }
    }
    gsync();

    /* ---- ph33: x_pool (float4) + scatter pooled edges (merged) ---- */
    {
        int M = g_M;
        const float4* x4 = (const float4*)x;
        float4* out4 = (float4*)out;
        for (int idx = gtid; idx < M * 32; idx += GT) {
            int m = idx >> 5, cg = idx & 31;
            int o = g_poff[m], L = g_pcnt[m];
            float4 s = make_float4(0.f, 0.f, 0.f, 0.f);
            for (int j = 0; j < L; j++) {
                float4 xv = x4[g_pnode[o + j] * 32 + cg];
                s.x += xv.x; s.y += xv.y; s.z += xv.z; s.w += xv.w;
            }
            float Lf = (float)L;
            float4 r;
            r.x = s.x / Lf; r.y = s.y / Lf; r.z = s.z / Lf; r.w = s.w / Lf;
            out4[m * 32 + cg] = r;
        }
    }
    for (int i = gtid; i < ED; i += GT) {
        int ns = g_ni[ei[i]], nd = g_ni[ei[ED + i]];
        if (ns != nd) {
            int pos = g_eoffA[ns] + atomicAdd(&g_fill4[ns], 1);
            g_bucket[pos] = nd;
        }
    }
    gsync();

    /* ---- ph37: per-cluster dedup (fused count+compact, small/large split) ---- */
    {
        int M = g_M;
        for (int m = gtid; m < M; m += GT) {
            int L = g_ecnt[m];
            if (L <= SMALL_L) {
                int o = g_eoffA[m];
                int buf[SMALL_L];
                for (int i = 0; i < L; i++) buf[i] = __ldcg(&g_bucket[o + i]);
                for (int i = 1; i < L; i++) {
                    int key = buf[i]; int j = i - 1;
                    while (j >= 0 && buf[j] > key) { buf[j + 1] = buf[j]; j--; }
                    buf[j + 1] = key;
                }
                int u = 0;
                for (int i = 0; i < L; i++) if (u == 0 || buf[i] != buf[u - 1]) buf[u++] = buf[i];
                for (int i = 0; i < u; i++) g_bucket[o + i] = buf[i];
                g_ucnt[m] = u;
            }
        }
        unsigned* mask = (unsigned*)SMEM;
        int* wsum = (int*)(SMEM + 2560);
        for (int m = b; m < M; m += G) {
            int L = g_ecnt[m];
            if (L <= SMALL_L) continue;
            int o = g_eoffA[m];
            __syncthreads();
            for (int w = t; w < MW; w += T) mask[w] = 0u;
            __syncthreads();
            for (int j = t; j < L; j += T) {
                int nd = __ldcg(&g_bucket[o + j]);
                atomicOr(&mask[nd >> 5], 1u << (nd & 31));
            }
            __syncthreads();
            int w0 = t * 3, ls = 0;
            #pragma unroll
            for (int k = 0; k < 3; k++) { int w = w0 + k; if (w < MW) ls += __popc(mask[w]); }
            int total;
            int off2 = bscan_excl(ls, wsum, &total);
            if (t == 0) g_ucnt[m] = total;
            #pragma unroll
            for (int k = 0; k < 3; k++) {
                int w = w0 + k; if (w >= MW) break;
                unsigned mw = mask[w];
                while (mw) {
                    int bit = __ffs(mw) - 1;
                    g_bucket[o + off2] = w * 32 + bit;
                    off2++;
                    mw &= mw - 1u;
                }
            }
            __syncthreads();
        }
    }
    gsync();

    /* ---- ph38: scan ucnt -> eoffB, total P ---- */
    scan_b0(g_ucnt, g_eoffB, NN, 3, SMEM);
    gsync();

    /* ---- ph39: emit pooled edges ---- */
    {
        int M = g_M;
        long base = 128L * M;
        int P = g_P;
        for (int m = b; m < M; m += G) {
            int o = g_eoffA[m], u = g_ucnt[m], ob = g_eoffB[m];
            for (int j = t; j < u; j += T) {
                int nd = __ldcg(&g_bucket[o + j]);
                out[base + ob + j] = (float)m;
                out[base + (long)P + ob + j] = (float)nd;
            }
        }
    }
    gsync();

    /* ---- ph40: tail outputs ---- */
    {
        int E = g_E, M = g_M, P = g_P;
        long base = 128L * M + 2L * P;
        for (int i = gtid; i < MAXE; i += GT) {
            if (i < M) out[base + i] = (float)batch[g_uniq[i]];
            if (i < E) out[base + M + i] = g_score[i];
            if (i < NN) out[base + M + E + i] = (float)g_ni[i];
        }
    }
}

/* ------------------------------ launch ------------------------------ */
extern "C" void kernel_launch(void* const* d_in, const int* in_sizes, int n_in,
                              void* d_out, int out_size) {
    const float* x      = (const float*)d_in[0];
    const float* W1     = (const float*)d_in[1];
    const float* b1     = (const float*)d_in[2];
    const float* gamma1 = (const float*)d_in[3];
    const float* beta1  = (const float*)d_in[4];
    const float* W2     = (const float*)d_in[5];
    const float* b2     = (const float*)d_in[6];
    const int*   ei     = (const int*)d_in[7];
    const int*   batch  = (const int*)d_in[8];
    float* out = (float*)d_out;

    mega<<<G, T>>>(x, W1, b1, gamma1, beta1, W2, b2, ei, batch, out);

    (void)in_sizes; (void)n_in; (void)out_size;
}

// round 14
// speedup vs baseline: 1.1297x; 1.1297x over previous
#include <cuda_runtime.h>
#include <math.h>

#define NN 20000
#define ED 160000
#define MAXE 160000
#define G 444
#define T 256
#define GT (G * T)
#define MW 625   /* bitmask words for NN bits */
#define SMALL_L 16

/* ------------------------------ scratch ------------------------------ */
__device__ int g_bar_cnt = 0;
__device__ int g_bar_gen = 0;

__device__ int g_cnt[NN], g_fill1[NN], g_fill2[NN], g_fill3[NN], g_fill4[NN];
__device__ int g_offA[NN], g_offB[NN];
__device__ int g_bucket[ED];
__device__ int g_csrc[MAXE], g_cdst[MAXE];
__device__ int g_ndeg[NN], g_incoff[NN];
__device__ int g_inc[2 * MAXE];
__device__ int g_inco[2 * MAXE];
__device__ float g_incd[2 * MAXE];
__device__ float g_dinv[MAXE];
__device__ float g_xW[NN * 64];
__device__ float g_aggN[NN * 64];
__device__ double g_p1[G * 64], g_p2[G * 64];
__device__ float g_mu[64], g_istd[64];
__device__ float g_h2[MAXE], g_agg2[NN], g_score[MAXE];
__device__ unsigned g_keyv[MAXE];
__device__ int g_hist2[65536];
__device__ unsigned long long g_packed[NN];
__device__ int g_bcnt[G], g_boff[G];
__device__ int g_n2c[NN], g_flag[NN], g_rankv[NN], g_uniq[NN], g_ni[NN];
__device__ int g_pcnt[NN], g_poff[NN], g_pnode[NN];
__device__ int g_ecnt[NN], g_eoffA[NN], g_ucnt[NN], g_eoffB[NN];
__device__ int g_E, g_M, g_P, g_krem;
__device__ unsigned g_prefix;

/* ------------------------------ grid barrier ------------------------------ */
__device__ __forceinline__ void gsync() {
    __syncthreads();
    if (threadIdx.x == 0) {
        int gen = *(volatile int*)&g_bar_gen;
        __threadfence();
        if (atomicAdd(&g_bar_cnt, 1) == G - 1) {
            g_bar_cnt = 0;
            __threadfence();
            *(volatile int*)&g_bar_gen = gen + 1;
        } else {
            while (*(volatile int*)&g_bar_gen == gen) __nanosleep(64);
        }
    }
    __syncthreads();
}

/* ---------------- block exclusive scan over T threads (shuffle) ---------------- */
__device__ __forceinline__ int bscan_excl(int v, int* sh, int* total) {
    int t = threadIdx.x, lane = t & 31, w = t >> 5;
    int x = v;
    #pragma unroll
    for (int o = 1; o < 32; o <<= 1) { int y = __shfl_up_sync(0xffffffffu, x, o); if (lane >= o) x += y; }
    if (lane == 31) sh[w] = x;
    __syncthreads();
    if (w == 0) {
        int s = (lane < 8) ? sh[lane] : 0;
        #pragma unroll
        for (int o = 1; o < 8; o <<= 1) { int y = __shfl_up_sync(0xffffffffu, s, o); if (lane >= o) s += y; }
        if (lane < 8) sh[lane] = s;
    }
    __syncthreads();
    *total = sh[7];
    int pre = (w == 0) ? 0 : sh[w - 1];
    return pre + x - v;
}

/* ---------------- block-0 exclusive scan over array ---------------- */
__device__ void scan_b0(const int* in, int* out, int n, int code, char* SMEM) {
    if (blockIdx.x != 0) return;
    int* sh = (int*)SMEM;
    int t = threadIdx.x;
    int per = (n + T - 1) / T;
    int lo = t * per; if (lo > n) lo = n;
    int hi = lo + per; if (hi > n) hi = n;
    int s = 0;
    for (int i = lo; i < hi; i++) s += __ldcg(in + i);
    int total;
    int excl = bscan_excl(s, sh, &total);
    if (t == 0) {
        if (code == 1) g_E = total;
        else if (code == 2) g_M = total;
        else if (code == 3) g_P = total;
    }
    int acc = excl;
    for (int i = lo; i < hi; i++) { int v = __ldcg(in + i); out[i] = acc; acc += v; }
}

/* ---------------- 16-bit radix pick (block 0) ---------------- */
__device__ void pick16_b0(int hi, char* SMEM) {
    if (blockIdx.x != 0) return;
    int* seg  = (int*)SMEM;
    int* sbin = (int*)SMEM + 256;
    int* info = (int*)SMEM + 512;
    int t = threadIdx.x;
    int s = 0, base = t * 256;
    for (int i = 0; i < 256; i++) s += __ldcg(&g_hist2[base + i]);
    seg[t] = s;
    __syncthreads();
    if (t == 0) {
        int krem = __ldcg(&g_krem);
        int cum = 0, sid = 0;
        for (int sg = 255; sg >= 0; sg--) { int h = seg[sg]; if (cum + h >= krem) { sid = sg; break; } cum += h; }
        info[0] = sid; info[1] = cum;
    }
    __syncthreads();
    int sid = info[0];
    sbin[t] = __ldcg(&g_hist2[sid * 256 + t]);
    __syncthreads();
    if (t == 0) {
        int krem = __ldcg(&g_krem);
        int cum = info[1], chosen = sid * 256;
        for (int bn = 255; bn >= 0; bn--) { int h = sbin[bn]; if (cum + h >= krem) { chosen = sid * 256 + bn; break; } cum += h; }
        g_prefix = __ldcg(&g_prefix) | ((unsigned)chosen << (hi ? 16 : 0));
        g_krem = krem - cum;
    }
    __syncthreads();
    if (hi) for (int i = t; i < 65536; i += T) g_hist2[i] = 0;
}

/* ------------------------------ megakernel ------------------------------ */
extern "C" __global__ void __launch_bounds__(T, 3)
mega(const float* __restrict__ x, const float* __restrict__ W1, const float* __restrict__ b1,
     const float* __restrict__ gamma1, const float* __restrict__ beta1,
     const float* __restrict__ W2, const float* __restrict__ b2,
     const int* __restrict__ ei, const int* __restrict__ batch,
     float* __restrict__ out) {
    __shared__ __align__(16) char SMEM[40960];
    const int t = threadIdx.x;
    const int b = blockIdx.x;
    const int gtid = b * T + t;

    /* ---- ph0: init ---- */
    for (int i = gtid; i < NN; i += GT) {
        g_cnt[i] = 0; g_fill1[i] = 0; g_fill2[i] = 0; g_fill3[i] = 0; g_fill4[i] = 0;
        g_ndeg[i] = 0; g_ecnt[i] = 0; g_pcnt[i] = 0; g_flag[i] = 0; g_ucnt[i] = 0;
        g_packed[i] = ~0ull;
    }
    for (int i = gtid; i < 65536; i += GT) g_hist2[i] = 0;
    gsync();

    /* ---- ph1: histogram of raw undirected edges by src ---- */
    for (int i = gtid; i < ED; i += GT) {
        int s = ei[i], d = ei[ED + i];
        if (s < d) atomicAdd(&g_cnt[s], 1);
    }
    gsync();

    /* ---- ph2: scan cnt -> offA ---- */
    scan_b0(g_cnt, g_offA, NN, 0, SMEM);
    gsync();

    /* ---- ph3: scatter to buckets ---- */
    for (int i = gtid; i < ED; i += GT) {
        int s = ei[i], d = ei[ED + i];
        if (s < d) {
            int pos = g_offA[s] + atomicAdd(&g_fill1[s], 1);
            g_bucket[pos] = d;
        }
    }
    gsync();

    /* ---- ph4: per-node sort + dedup (registerized) ---- */
    for (int u = gtid; u < NN; u += GT) {
        int o = g_offA[u], L = g_cnt[u], m = 0;
        if (L <= 24) {
            int buf[24];
            for (int i = 0; i < L; i++) buf[i] = g_bucket[o + i];
            for (int i = 1; i < L; i++) {
                int key = buf[i]; int j = i - 1;
                while (j >= 0 && buf[j] > key) { buf[j + 1] = buf[j]; j--; }
                buf[j + 1] = key;
            }
            int last = -1;
            for (int i = 0; i < L; i++) {
                int v = buf[i];
                if (v != last) { g_bucket[o + m++] = v; last = v; }
            }
        } else {
            for (int i = 1; i < L; i++) {
                int key = g_bucket[o + i]; int j = i - 1;
                while (j >= 0 && g_bucket[o + j] > key) { g_bucket[o + j + 1] = g_bucket[o + j]; j--; }
                g_bucket[o + j + 1] = key;
            }
            for (int i = 0; i < L; i++) {
                int v = g_bucket[o + i];
                if (m == 0 || v != g_bucket[o + m - 1]) g_bucket[o + m++] = v;
            }
        }
        g_cnt[u] = m;
    }
    gsync();

    /* ---- ph5: scan deduped counts -> offB, total E ---- */
    scan_b0(g_cnt, g_offB, NN, 1, SMEM);
    gsync();

    /* ---- ph6: compact clean edge list + node degrees ---- */
    for (int u = gtid; u < NN; u += GT) {
        int L = g_cnt[u], ob = g_offB[u], oa = g_offA[u];
        for (int j = 0; j < L; j++) {
            int d = g_bucket[oa + j];
            g_csrc[ob + j] = u; g_cdst[ob + j] = d;
            atomicAdd(&g_ndeg[d], 1);
        }
        if (L) atomicAdd(&g_ndeg[u], L);
    }
    gsync();

    /* ---- ph7: scan ndeg -> incoff ---- */
    scan_b0(g_ndeg, g_incoff, NN, 0, SMEM);
    gsync();

    /* ---- ph8: incidence scatter + dinv (split segments; src slots direct) ---- */
    {
        int E = g_E;
        for (int e = gtid; e < E; e += GT) {
            int u = g_csrc[e], v = g_cdst[e];
            int srcbase = g_incoff[u] + (g_ndeg[u] - g_cnt[u]);
            g_inc[srcbase + (e - g_offB[u])] = e;                 /* no atomic */
            int p2 = g_incoff[v] + atomicAdd(&g_fill2[v], 1); g_inc[p2] = e;
            int deg = g_ndeg[u] + g_ndeg[v] - 1;
            if (deg < 1) deg = 1;
            g_dinv[e] = 1.0f / sqrtf((float)deg);
        }
    }
    gsync();

    /* ---- ph9: sort ONLY dst-segment (result = full ascending list) +
       fill (other,dinv) slots + GEMM ---- */
    for (int u = gtid; u < NN; u += GT) {
        int o = g_incoff[u], L = g_ndeg[u];
        int dl = L - g_cnt[u];
        if (dl > 1) {
            if (dl <= 24) {
                int buf[24];
                for (int i = 0; i < dl; i++) buf[i] = g_inc[o + i];
                for (int i = 1; i < dl; i++) {
                    int key = buf[i]; int j = i - 1;
                    while (j >= 0 && buf[j] > key) { buf[j + 1] = buf[j]; j--; }
                    buf[j + 1] = key;
                }
                for (int i = 0; i < dl; i++) g_inc[o + i] = buf[i];
            } else {
                for (int i = 1; i < dl; i++) {
                    int key = g_inc[o + i]; int j = i - 1;
                    while (j >= 0 && g_inc[o + j] > key) { g_inc[o + j + 1] = g_inc[o + j]; j--; }
                    g_inc[o + j + 1] = key;
                }
            }
        }
        for (int j = 0; j < L; j++) {
            int e = g_inc[o + j];
            g_inco[o + j] = g_csrc[e] + g_cdst[e] - u;
            g_incd[o + j] = g_dinv[e];
        }
    }
    {
        /* register-tiled GEMM: 16 rows per group, 4 rows per thread */
        float* sW = (float*)SMEM;
        float* sx = (float*)(SMEM + 32768);
        __syncthreads();
        for (int i = t; i < 128 * 64; i += T) sW[i] = W1[i];
        __syncthreads();
        int c = t & 63, q = t >> 6;
        int rb = q * 4;
        for (int grp = b; grp < NN / 16; grp += G) {
            int r0 = grp * 16;
            float4* sx4 = (float4*)sx;
            const float4* x4 = (const float4*)(x + (long)r0 * 128);
            for (int i = t; i < 512; i += T) sx4[i] = x4[i];
            __syncthreads();
            float a0 = 0.f, a1 = 0.f, a2 = 0.f, a3 = 0.f;
            #pragma unroll 4
            for (int k2 = 0; k2 < 128; k2++) {
                float w = sW[k2 * 64 + c];
                a0 += sx[(rb + 0) * 128 + k2] * w;
                a1 += sx[(rb + 1) * 128 + k2] * w;
                a2 += sx[(rb + 2) * 128 + k2] * w;
                a3 += sx[(rb + 3) * 128 + k2] * w;
            }
            g_xW[(r0 + rb + 0) * 64 + c] = a0;
            g_xW[(r0 + rb + 1) * 64 + c] = a1;
            g_xW[(r0 + rb + 2) * 64 + c] = a2;
            g_xW[(r0 + rb + 3) * 64 + c] = a3;
            __syncthreads();
        }
    }
    gsync();

    /* ---- ph11: aggN, float4 channels (per-channel math identical) ---- */
    {
        const float4* xW4 = (const float4*)g_xW;
        float4* aN4 = (float4*)g_aggN;
        for (int idx = gtid; idx < NN * 16; idx += GT) {
            int n = idx >> 4, cg = idx & 15;
            int o = g_incoff[n], L = g_ndeg[n];
            float4 xn = xW4[n * 16 + cg];
            float4 s = make_float4(0.f, 0.f, 0.f, 0.f);
            for (int j = 0; j < L; j++) {
                int other = g_inco[o + j];
                float di = g_incd[o + j];
                float4 xo = xW4[other * 16 + cg];
                s.x += di * (0.5f * (xn.x + xo.x));
                s.y += di * (0.5f * (xn.y + xo.y));
                s.z += di * (0.5f * (xn.z + xo.z));
                s.w += di * (0.5f * (xn.w + xo.w));
            }
            aN4[idx] = s;
        }
    }
    gsync();

    /* ---- ph12: BN stats over conv1 output (recomputed on the fly, per-channel) ---- */
    {
        int E = g_E;
        double s = 0.0, s2 = 0.0;
        float bc = b1[t & 63];
        for (int idx = gtid; idx < E * 64; idx += GT) {
            int e = idx >> 6, c = idx & 63;
            int u = g_csrc[e], v = g_cdst[e];
            float di = g_dinv[e];
            float h = 0.5f * (g_xW[u * 64 + c] + g_xW[v * 64 + c]);
            float z = di * (g_aggN[u * 64 + c] + g_aggN[v * 64 + c]) - di * di * h + bc;
            double zd = (double)z;
            s += zd; s2 += zd * zd;
        }
        double* sA = (double*)SMEM;
        double* sB = (double*)(SMEM + 2048);
        sA[t] = s; sB[t] = s2;
        __syncthreads();
        if (t < 64) {
            g_p1[b * 64 + t] = sA[t] + sA[t + 64] + sA[t + 128] + sA[t + 192];
            g_p2[b * 64 + t] = sB[t] + sB[t + 64] + sB[t + 128] + sB[t + 192];
        }
    }
    gsync();

    /* ---- ph13: BN finalize + top-k init ---- */
    if (b == 0 && t < 64) {
        double s = 0.0, s2 = 0.0;
        for (int bb = 0; bb < G; bb++) { s += g_p1[bb * 64 + t]; s2 += g_p2[bb * 64 + t]; }
        double Ed = (double)g_E;
        double mu = s / Ed;
        double var = s2 / Ed - mu * mu;
        g_mu[t] = (float)mu;
        g_istd[t] = (float)(1.0 / sqrt(var + 1e-5));
        if (t == 0) {
            int E = g_E;
            int k = E / 2;
            if (k > NN / 2) k = NN / 2;
            if (k < 1) k = 1;
            g_krem = k; g_prefix = 0u;
        }
    }
    gsync();

    /* ---- ph14: BN+ReLU+dot -> h2 (conv1 recomputed, warp per edge) ---- */
    {
        int E = g_E;
        int lane = t & 31;
        float ga0 = gamma1[lane],      be0 = beta1[lane],      w20 = W2[lane],      bb0 = b1[lane];
        float ga1 = gamma1[lane + 32], be1 = beta1[lane + 32], w21 = W2[lane + 32], bb1 = b1[lane + 32];
        float mu0 = g_mu[lane], is0 = g_istd[lane], mu1 = g_mu[lane + 32], is1 = g_istd[lane + 32];
        for (int gt = gtid; gt < E * 32; gt += GT) {
            int e = gt >> 5;
            int u = g_csrc[e], v = g_cdst[e];
            float di = g_dinv[e], di2 = di * di;
            float h0 = 0.5f * (g_xW[u * 64 + lane] + g_xW[v * 64 + lane]);
            float z0 = di * (g_aggN[u * 64 + lane] + g_aggN[v * 64 + lane]) - di2 * h0 + bb0;
            float h1 = 0.5f * (g_xW[u * 64 + 32 + lane] + g_xW[v * 64 + 32 + lane]);
            float z1 = di * (g_aggN[u * 64 + 32 + lane] + g_aggN[v * 64 + 32 + lane]) - di2 * h1 + bb1;
            float a0 = fmaxf(ga0 * (z0 - mu0) * is0 + be0, 0.f);
            float a1 = fmaxf(ga1 * (z1 - mu1) * is1 + be1, 0.f);
            float d = a0 * w20 + a1 * w21;
            #pragma unroll
            for (int o = 16; o > 0; o >>= 1) d += __shfl_down_sync(0xffffffffu, d, o);
            if (lane == 0) g_h2[e] = d;
        }
    }
    gsync();

    /* ---- ph15: agg2 per node ---- */
    for (int n = gtid; n < NN; n += GT) {
        int o = g_incoff[n], L = g_ndeg[n];
        float s = 0.f;
        for (int j = 0; j < L; j++) { int e = g_inc[o + j]; s += g_incd[o + j] * g_h2[e]; }
        g_agg2[n] = s;
    }
    gsync();

    /* ---- ph16: scores + 16-bit radix hist (hi) ---- */
    {
        int E = g_E;
        float bias2 = b2[0];
        for (int e = gtid; e < E; e += GT) {
            float di = g_dinv[e];
            float z = di * (g_agg2[g_csrc[e]] + g_agg2[g_cdst[e]]) - di * di * g_h2[e] + bias2;
            float s = 1.0f / (1.0f + expf(-z));
            g_score[e] = s;
            unsigned kk = __float_as_uint(s);
            g_keyv[e] = kk;
            atomicAdd(&g_hist2[kk >> 16], 1);
        }
    }
    gsync();

    /* ---- ph17: pick hi 16 bits ---- */
    pick16_b0(1, SMEM);
    gsync();

    /* ---- ph18: hist low 16 bits for matching hi prefix ---- */
    {
        int E = g_E;
        unsigned hiP = __ldcg(&g_prefix) >> 16;
        for (int e = gtid; e < E; e += GT) {
            unsigned kk = g_keyv[e];
            if ((kk >> 16) == hiP) atomicAdd(&g_hist2[kk & 0xFFFFu], 1);
        }
    }
    gsync();

    /* ---- ph19: pick low 16 bits ---- */
    pick16_b0(0, SMEM);
    gsync();

    /* ---- ph24: strictly-greater -> atomicMin cluster; count eq per block ---- */
    {
        int E = g_E;
        unsigned Tp = __ldcg(&g_prefix);
        int cb = (E + G - 1) / G;
        int lo = b * cb, hi = lo + cb; if (hi > E) hi = E;
        int cnt = 0;
        for (int base = lo; base < hi; base += T) {
            int i = base + t;
            if (i < hi) {
                unsigned kk = g_keyv[i];
                if (kk > Tp) {
                    unsigned long long pk = (((unsigned long long)kk) << 32) | (unsigned)(0xFFFFFFFFu - (unsigned)i);
                    atomicMin(&g_packed[g_cdst[i]], pk);
                }
                if (kk == Tp) cnt++;
            }
        }
        int* sh = (int*)SMEM;
        int total;
        bscan_excl(cnt, sh, &total);
        if (t == 0) g_bcnt[b] = total;
    }
    gsync();

    /* ---- ph25: scan bcnt -> boff ---- */
    scan_b0(g_bcnt, g_boff, G, 0, SMEM);
    gsync();

    /* ---- ph26: eq keys, index-ordered rank < krem -> select ---- */
    {
        int E = g_E;
        unsigned Tp = __ldcg(&g_prefix);
        int krem = __ldcg(&g_krem);
        int cb = (E + G - 1) / G;
        int lo = b * cb, hi = lo + cb; if (hi > E) hi = E;
        int* ws = (int*)SMEM;
        int* scarry = (int*)SMEM + 16;
        if (t == 0) *scarry = 0;
        __syncthreads();
        int lane = t & 31, wid = t >> 5;
        for (int base = lo; base < hi; base += T) {
            int i = base + t;
            int eq = (i < hi && g_keyv[i] == Tp) ? 1 : 0;
            unsigned bal = __ballot_sync(0xffffffffu, eq);
            if (lane == 0) ws[wid] = __popc(bal);
            __syncthreads();
            int pre = 0;
            for (int k = 0; k < wid; k++) pre += ws[k];
            int lexcl = pre + __popc(bal & ((1u << lane) - 1u));
            if (eq) {
                int rank = g_boff[b] + *scarry + lexcl;
                if (rank < krem) {
                    unsigned long long pk = (((unsigned long long)Tp) << 32) | (unsigned)(0xFFFFFFFFu - (unsigned)i);
                    atomicMin(&g_packed[g_cdst[i]], pk);
                }
            }
            __syncthreads();
            if (t == 0) {
                int tot = 0;
                #pragma unroll
                for (int k = 0; k < 8; k++) tot += ws[k];
                *scarry += tot;
            }
            __syncthreads();
        }
    }
    gsync();

    /* ---- ph27: node -> cluster label ---- */
    for (int n = gtid; n < NN; n += GT) {
        unsigned long long pk = g_packed[n];
        int v;
        if (pk != ~0ull) {
            unsigned e = 0xFFFFFFFFu - (unsigned)(pk & 0xFFFFFFFFull);
            v = g_csrc[e];
        } else v = n;
        g_n2c[n] = v;
        g_flag[v] = 1;
    }
    gsync();

    /* ---- ph28: scan flag -> rankv, total M ---- */
    scan_b0(g_flag, g_rankv, NN, 2, SMEM);
    gsync();

    /* ---- ph29: maps + pool counts ---- */
    for (int n = gtid; n < NN; n += GT) {
        if (g_flag[n]) g_uniq[g_rankv[n]] = n;
        int m = g_rankv[g_n2c[n]];
        g_ni[n] = m;
        atomicAdd(&g_pcnt[m], 1);
    }
    gsync();

    /* ---- ph30: scan pcnt -> poff ---- */
    scan_b0(g_pcnt, g_poff, NN, 0, SMEM);
    gsync();

    /* ---- ph31: scatter members + pooled-edge histogram (merged) ---- */
    for (int n = gtid; n < NN; n += GT) {
        int m = g_ni[n];
        int pos = g_poff[m] + atomicAdd(&g_fill3[m], 1);
        g_pnode[pos] = n;
    }
    for (int i = gtid; i < ED; i += GT) {
        int ns = g_ni[ei[i]], nd = g_ni[ei[ED + i]];
        if (ns != nd) atomicAdd(&g_ecnt[ns], 1);
    }
    gsync();

    /* ---- ph32: scan ecnt -> eoffA (b0) + member-list sorts ---- */
    scan_b0(g_ecnt, g_eoffA, NN, 0, SMEM);
    {
        int M = g_M;
        for (int m = gtid; m < M; m += GT) {
            int o = g_poff[m], L = g_pcnt[m];
            if (L <= 16) {
                int buf[16];
                for (int i = 0; i < L; i++) buf[i] = g_pnode[o + i];
                for (int i = 1; i < L; i++) {
                    int key = buf[i]; int j = i - 1;
                    while (j >= 0 && buf[j] > key) { buf[j + 1] = buf[j]; j--; }
                    buf[j + 1] = key;
                }
                for (int i = 0; i < L; i++) g_pnode[o + i] = buf[i];
            } else {
                for (int i = 1; i < L; i++) {
                    int key = g_pnode[o + i]; int j = i - 1;
                    while (j >= 0 && g_pnode[o + j] > key) { g_pnode[o + j + 1] = g_pnode[o + j]; j--; }
                    g_pnode[o + j + 1] = key;
                }
            }
        }
    }
    gsync();

    /* ---- ph33: x_pool (float4) + scatter pooled edges (merged) ---- */
    {
        int M = g_M;
        const float4* x4 = (const float4*)x;
        float4* out4 = (float4*)out;
        for (int idx = gtid; idx < M * 32; idx += GT) {
            int m = idx >> 5, cg = idx & 31;
            int o = g_poff[m], L = g_pcnt[m];
            float4 s = make_float4(0.f, 0.f, 0.f, 0.f);
            for (int j = 0; j < L; j++) {
                float4 xv = x4[g_pnode[o + j] * 32 + cg];
                s.x += xv.x; s.y += xv.y; s.z += xv.z; s.w += xv.w;
            }
            float Lf = (float)L;
            float4 r;
            r.x = s.x / Lf; r.y = s.y / Lf; r.z = s.z / Lf; r.w = s.w / Lf;
            out4[m * 32 + cg] = r;
        }
    }
    for (int i = gtid; i < ED; i += GT) {
        int ns = g_ni[ei[i]], nd = g_ni[ei[ED + i]];
        if (ns != nd) {
            int pos = g_eoffA[ns] + atomicAdd(&g_fill4[ns], 1);
            g_bucket[pos] = nd;
        }
    }
    gsync();

    /* ---- ph37: per-cluster dedup (fused count+compact, small/large split) ---- */
    {
        int M = g_M;
        for (int m = gtid; m < M; m += GT) {
            int L = g_ecnt[m];
            if (L <= SMALL_L) {
                int o = g_eoffA[m];
                int buf[SMALL_L];
                for (int i = 0; i < L; i++) buf[i] = __ldcg(&g_bucket[o + i]);
                for (int i = 1; i < L; i++) {
                    int key = buf[i]; int j = i - 1;
                    while (j >= 0 && buf[j] > key) { buf[j + 1] = buf[j]; j--; }
                    buf[j + 1] = key;
                }
                int u = 0;
                for (int i = 0; i < L; i++) if (u == 0 || buf[i] != buf[u - 1]) buf[u++] = buf[i];
                for (int i = 0; i < u; i++) g_bucket[o + i] = buf[i];
                g_ucnt[m] = u;
            }
        }
        unsigned* mask = (unsigned*)SMEM;
        int* wsum = (int*)(SMEM + 2560);
        for (int m = b; m < M; m += G) {
            int L = g_ecnt[m];
            if (L <= SMALL_L) continue;
            int o = g_eoffA[m];
            __syncthreads();
            for (int w = t; w < MW; w += T) mask[w] = 0u;
            __syncthreads();
            for (int j = t; j < L; j += T) {
                int nd = __ldcg(&g_bucket[o + j]);
                atomicOr(&mask[nd >> 5], 1u << (nd & 31));
            }
            __syncthreads();
            int w0 = t * 3, ls = 0;
            #pragma unroll
            for (int k = 0; k < 3; k++) { int w = w0 + k; if (w < MW) ls += __popc(mask[w]); }
            int total;
            int off2 = bscan_excl(ls, wsum, &total);
            if (t == 0) g_ucnt[m] = total;
            #pragma unroll
            for (int k = 0; k < 3; k++) {
                int w = w0 + k; if (w >= MW) break;
                unsigned mw = mask[w];
                while (mw) {
                    int bit = __ffs(mw) - 1;
                    g_bucket[o + off2] = w * 32 + bit;
                    off2++;
                    mw &= mw - 1u;
                }
            }
            __syncthreads();
        }
    }
    gsync();

    /* ---- ph38: scan ucnt -> eoffB, total P ---- */
    scan_b0(g_ucnt, g_eoffB, NN, 3, SMEM);
    gsync();

    /* ---- ph39: emit pooled edges ---- */
    {
        int M = g_M;
        long base = 128L * M;
        int P = g_P;
        for (int m = b; m < M; m += G) {
            int o = g_eoffA[m], u = g_ucnt[m], ob = g_eoffB[m];
            for (int j = t; j < u; j += T) {
                int nd = __ldcg(&g_bucket[o + j]);
                out[base + ob + j] = (float)m;
                out[base + (long)P + ob + j] = (float)nd;
            }
        }
    }
    gsync();

    /* ---- ph40: tail outputs ---- */
    {
        int E = g_E, M = g_M, P = g_P;
        long base = 128L * M + 2L * P;
        for (int i = gtid; i < MAXE; i += GT) {
            if (i < M) out[base + i] = (float)batch[g_uniq[i]];
            if (i < E) out[base + M + i] = g_score[i];
            if (i < NN) out[base + M + E + i] = (float)g_ni[i];
        }
    }
}

/* ------------------------------ launch ------------------------------ */
extern "C" void kernel_launch(void* const* d_in, const int* in_sizes, int n_in,
                              void* d_out, int out_size) {
    const float* x      = (const float*)d_in[0];
    const float* W1     = (const float*)d_in[1];
    const float* b1     = (const float*)d_in[2];
    const float* gamma1 = (const float*)d_in[3];
    const float* beta1  = (const float*)d_in[4];
    const float* W2     = (const float*)d_in[5];
    const float* b2     = (const float*)d_in[6];
    const int*   ei     = (const int*)d_in[7];
    const int*   batch  = (const int*)d_in[8];
    float* out = (float*)d_out;

    mega<<<G, T>>>(x, W1, b1, gamma1, beta1, W2, b2, ei, batch, out);

    (void)in_sizes; (void)n_in; (void)out_size;
}